// round 14
// baseline (speedup 1.0000x reference)
#include <cuda_runtime.h>

typedef unsigned long long u64;

__device__ float g_h2[32768 * 32];

__device__ __forceinline__ void fma2(u64 &acc, u64 a, u64 b){
  asm("fma.rn.f32x2 %0, %1, %2, %0;" : "+l"(acc) : "l"(a), "l"(b));
}
__device__ __forceinline__ float2 unpk(u64 v){
  float2 f; asm("mov.b64 {%0,%1}, %2;" : "=f"(f.x), "=f"(f.y) : "l"(v)); return f;
}

// ================= MADE (frozen, Round-4 proven) =================
#define MR 64
__global__ __launch_bounds__(MR)
void made_kernel(const float* __restrict__ x,
                 const float* __restrict__ W1, const float* __restrict__ b1,
                 const float* __restrict__ W2, const float* __restrict__ b2,
                 int B)
{
  extern __shared__ float smem[];
  float* xs  = smem;            // MR*66
  float* wsh = smem + MR*66;    // 6144 raw W1(4096)+W2(2048)

  const int tid  = threadIdx.x;
  const int row0 = blockIdx.x * MR;

  for (int idx = tid; idx < MR*64; idx += MR)
    xs[(idx>>6)*66 + (idx&63)] = x[(size_t)row0*64 + idx];
  for (int idx = tid; idx < 6144; idx += MR)
    wsh[idx] = (idx < 4096) ? W1[idx] : W2[idx-4096];
  __syncthreads();

  u64 xp[32];
  {
    const u64* xr = (const u64*)(xs + tid*66);
    #pragma unroll
    for (int k=0;k<32;k++) xp[k] = xr[k];
  }

  float h1f[64];
  #pragma unroll
  for (int j = 0; j < 64; j++){
    const int jj = j % 63;
    const float* wrow = wsh + j*64;
    const u64* wr = (const u64*)wrow;
    u64 a0=0ull,a1=0ull,a2=0ull,a3=0ull;
    #pragma unroll
    for (int k = 0; k < 32; k++){
      if (2*k + 1 <= jj){
        if      ((k&3)==0) fma2(a0, xp[k], wr[k]);
        else if ((k&3)==1) fma2(a1, xp[k], wr[k]);
        else if ((k&3)==2) fma2(a2, xp[k], wr[k]);
        else               fma2(a3, xp[k], wr[k]);
      }
    }
    float2 s0=unpk(a0), s1=unpk(a1), s2=unpk(a2), s3=unpk(a3);
    float s = ((s0.x+s0.y)+(s1.x+s1.y)) + ((s2.x+s2.y)+(s3.x+s3.y));
    if ((jj & 1) == 0) s = fmaf(unpk(xp[jj>>1]).x, wrow[jj], s);
    h1f[j] = fmaxf(s + __ldg(b1 + j), 0.f);
  }

  #pragma unroll
  for (int j = 0; j < 32; j++){
    const float* wrow = wsh + 4096 + j*64;
    float a0=0.f,a1=0.f,a2=0.f,a3=0.f;
    #pragma unroll
    for (int i = 0; i < 63; i++){
      if (i <= j){
        if      ((i&3)==0) a0 = fmaf(h1f[i], wrow[i], a0);
        else if ((i&3)==1) a1 = fmaf(h1f[i], wrow[i], a1);
        else if ((i&3)==2) a2 = fmaf(h1f[i], wrow[i], a2);
        else               a3 = fmaf(h1f[i], wrow[i], a3);
      }
    }
    a0 = fmaf(h1f[63], wrow[63], a0);
    float s = ((a0+a1)+(a2+a3)) + __ldg(b2 + j);
    xs[tid*66 + j] = fmaxf(s, 0.f);
  }
  __syncthreads();
  for (int idx = tid; idx < MR*32; idx += MR)
    g_h2[(size_t)row0*32 + idx] = xs[(idx>>5)*66 + (idx&31)];
}

// ================= spline: projection + RQ spline (short live ranges) =================
template<int KM, int CNT>
__device__ __forceinline__ void pvb(float* o, const u64* h2p,
                                    const float* slab, const float* bb, int m0)
{
  #pragma unroll
  for (int mm = 0; mm < CNT; mm++){
    int m = m0 + mm;
    const ulonglong2* W = (const ulonglong2*)(slab + m*32);
    u64 a0 = 0ull, a1 = 0ull;
    #pragma unroll
    for (int k = 0; k < KM; k++){
      ulonglong2 w = W[k];
      fma2(a0, h2p[2*k],   w.x);
      fma2(a1, h2p[2*k+1], w.y);
    }
    float2 s0 = unpk(a0), s1 = unpk(a1);
    o[mm] = s0.x + s0.y + s1.x + s1.y + bb[m];
  }
}

__device__ __forceinline__ void softmax_cum(const float* v, float* cum)
{
  float mx = v[0];
  #pragma unroll
  for (int k=1;k<8;k++) mx = fmaxf(mx, v[k]);
  float ev[8], s = 0.f;
  #pragma unroll
  for (int k=0;k<8;k++){ ev[k] = __expf(v[k]-mx); s += ev[k]; }
  float inv = 1.0f / s;
  cum[0] = -3.f; float c = 0.f;
  #pragma unroll
  for (int k=0;k<7;k++){ c += 1e-3f + 0.992f*(ev[k]*inv); cum[k+1] = fmaf(6.f, c, -3.f); }
  cum[8] = 3.f;
}

template<int KM>
__device__ __forceinline__ void spline_body(const float* h2row, const float* slabs,
                                            const float* b3s, int ds,
                                            const float* xin, float* y2, float& ldacc)
{
  u64 h2p[2*KM];
  {
    const u64* hp = (const u64*)h2row;
    #pragma unroll
    for (int k = 0; k < 2*KM; k++) h2p[k] = hp[k];
  }
  #pragma unroll
  for (int p = 0; p < 2; p++){
    const int c = ds*2 + p;
    const float* slab = slabs + c*768;
    const float* bb   = b3s + c*24;

    float xv = xin[p];
    float xc = fminf(fmaxf(xv, -3.f), 3.f);
    bool inside = (xv >= -3.f) && (xv <= 3.f);

    float t8[8];
    int bi; float xk, xk1;
    // --- widths: softmax + bin search + select, cum array dies here ---
    pvb<KM,8>(t8, h2p, slab, bb, 0);
    {
      float cum[9];
      softmax_cum(t8, cum);
      int cnt = 0;
      #pragma unroll
      for (int k=0;k<9;k++) cnt += (xc >= cum[k] + 1e-6f) ? 1 : 0;
      bi = cnt - 1; bi = bi < 0 ? 0 : (bi > 7 ? 7 : bi);
      xk = cum[0]; xk1 = cum[1];
      #pragma unroll
      for (int k=1;k<8;k++){
        bool m = (bi == k);
        xk  = m ? cum[k]   : xk;
        xk1 = m ? cum[k+1] : xk1;
      }
    }
    // --- heights: softmax + select, cum array dies here ---
    float yk, yk1;
    pvb<KM,8>(t8, h2p, slab, bb, 8);
    {
      float cum[9];
      softmax_cum(t8, cum);
      yk = cum[0]; yk1 = cum[1];
      #pragma unroll
      for (int k=1;k<8;k++){
        bool m = (bi == k);
        yk  = m ? cum[k]   : yk;
        yk1 = m ? cum[k+1] : yk1;
      }
    }
    // --- derivatives: select the two needed, softplus only those ---
    float dk, dk1;
    pvb<KM,7>(t8, h2p, slab, bb, 16);
    {
      float va = t8[0], vb = t8[0];
      #pragma unroll
      for (int k=1;k<7;k++){
        va = (bi - 1 == k) ? t8[k] : va;   // der[bi]   = f(t8[bi-1])
        vb = (bi == k)     ? t8[k] : vb;   // der[bi+1] = f(t8[bi])
      }
      float spa = fmaxf(va, 0.f) + __logf(1.f + __expf(-fabsf(va)));
      float spb = fmaxf(vb, 0.f) + __logf(1.f + __expf(-fabsf(vb)));
      dk  = (bi == 0) ? 1.f : (1e-3f + spa);
      dk1 = (bi == 7) ? 1.f : (1e-3f + spb);
    }
    // --- rational-quadratic evaluation from scalars only ---
    float wk = xk1 - xk, hk = yk1 - yk;
    float invwk = 1.0f / wk;
    float delta = hk * invwk;
    float th  = (xc - xk) * invwk;
    float omt = 1.f - th;
    float tt  = th * omt;
    float th2 = th * th;
    float num = hk * (delta*th2 + dk*tt);
    float den = delta + (dk + dk1 - 2.f*delta) * tt;
    float y   = yk + num / den;
    float dnum = delta*delta * (dk1*th2 + 2.f*delta*tt + dk*omt*omt);
    float ldv  = __logf(dnum) - 2.f*__logf(den);

    y2[p]  = inside ? y   : xv;
    ldacc += inside ? ldv : 0.f;
  }
}

__global__ __launch_bounds__(256, 3)
void spline_kernel(const float* __restrict__ x,
                   const float* __restrict__ W3, const float* __restrict__ b3,
                   float* __restrict__ out, int B)
{
  __shared__ __align__(16) float h2s[128*34];
  __shared__ __align__(16) float slabs[4*768];
  __shared__ float b3s[96];
  __shared__ __align__(16) float zsm[512];
  __shared__ float lsum[256];

  const int tid  = threadIdx.x;
  const int r    = tid & 127;
  const int ds   = tid >> 7;
  const int row0 = blockIdx.x * 128;
  const int g    = blockIdx.y;
  const int D0   = g * 4;
  const int kmax = (g + 1 < 8) ? (g + 1) : 8;

  // stage h2 tile
  {
    const float2* src = (const float2*)(g_h2 + (size_t)row0*32);
    #pragma unroll
    for (int it = 0; it < 8; it++){
      int idx = tid + it*256;
      int rr = idx >> 4, cc = idx & 15;
      *(float2*)(h2s + rr*34 + cc*2) = src[idx];
    }
  }
  // stage 4 W3 slabs directly from raw W3, applying the MADE mask inline
  #pragma unroll
  for (int it = 0; it < 12; it++){
    int idx = tid + it*256;          // 0..3071
    int dt  = idx / 768;
    int rem = idx - dt*768;
    int m   = rem >> 5, i = rem & 31;
    int d   = D0 + dt;
    float v = 0.f;
    if (m < 23 && i < d) v = __ldg(W3 + (m*64 + d)*32 + i);
    slabs[idx] = v;
  }
  if (tid < 96){
    int dt = tid / 24, m = tid % 24;
    b3s[tid] = (m < 23) ? __ldg(b3 + m*64 + D0 + dt) : 0.f;
  }
  __syncthreads();

  float2 xv2 = *(const float2*)(x + (size_t)(row0 + r)*64 + D0 + ds*2);
  float xin[2] = {xv2.x, xv2.y};
  float y2[2];
  float ldacc = 0.f;
  const float* h2row = h2s + r*34;

  switch (kmax){
    case 1: spline_body<1>(h2row, slabs, b3s, ds, xin, y2, ldacc); break;
    case 2: spline_body<2>(h2row, slabs, b3s, ds, xin, y2, ldacc); break;
    case 3: spline_body<3>(h2row, slabs, b3s, ds, xin, y2, ldacc); break;
    case 4: spline_body<4>(h2row, slabs, b3s, ds, xin, y2, ldacc); break;
    case 5: spline_body<5>(h2row, slabs, b3s, ds, xin, y2, ldacc); break;
    case 6: spline_body<6>(h2row, slabs, b3s, ds, xin, y2, ldacc); break;
    case 7: spline_body<7>(h2row, slabs, b3s, ds, xin, y2, ldacc); break;
    default: spline_body<8>(h2row, slabs, b3s, ds, xin, y2, ldacc); break;
  }

  zsm[r*4 + ds*2 + 0] = y2[0];
  zsm[r*4 + ds*2 + 1] = y2[1];
  lsum[tid] = ldacc;
  __syncthreads();

  if (tid < 128){
    float4 v = *(const float4*)(zsm + tid*4);
    *(float4*)(out + (size_t)(row0 + tid)*64 + D0) = v;
    atomicAdd(out + (size_t)B*64 + row0 + tid, lsum[tid] + lsum[tid + 128]);
  }
}

// ================= launch =================
extern "C" void kernel_launch(void* const* d_in, const int* in_sizes, int n_in,
                              void* d_out, int out_size)
{
  const float* x  = (const float*)d_in[0];
  const float* W1 = (const float*)d_in[1];
  const float* b1 = (const float*)d_in[2];
  const float* W2 = (const float*)d_in[3];
  const float* b2 = (const float*)d_in[4];
  const float* W3 = (const float*)d_in[5];
  const float* b3 = (const float*)d_in[6];
  float* out = (float*)d_out;

  int B = in_sizes[0] / 64;
  int smemA = (MR*66 + 6144) * (int)sizeof(float);   // 41472

  cudaFuncSetAttribute(made_kernel,
                       cudaFuncAttributeMaxDynamicSharedMemorySize, smemA);

  // zero the log-det accumulator region (graph-capturable async memset)
  cudaMemsetAsync(out + (size_t)B*64, 0, (size_t)B * sizeof(float));

  made_kernel<<<B/MR, MR, smemA>>>(x, W1, b1, W2, b2, B);
  spline_kernel<<<dim3(B/128, 16), 256>>>(x, W3, b3, out, B);
}

// round 15
// speedup vs baseline: 1.0389x; 1.0389x over previous
#include <cuda_runtime.h>

typedef unsigned long long u64;

__device__ float g_h2[32768 * 32];

__device__ __forceinline__ void fma2(u64 &acc, u64 a, u64 b){
  asm("fma.rn.f32x2 %0, %1, %2, %0;" : "+l"(acc) : "l"(a), "l"(b));
}
__device__ __forceinline__ float2 unpk(u64 v){
  float2 f; asm("mov.b64 {%0,%1}, %2;" : "=f"(f.x), "=f"(f.y) : "l"(v)); return f;
}

// ================= MADE (frozen, Round-4 proven) =================
#define MR 64
__global__ __launch_bounds__(MR)
void made_kernel(const float* __restrict__ x,
                 const float* __restrict__ W1, const float* __restrict__ b1,
                 const float* __restrict__ W2, const float* __restrict__ b2,
                 int B)
{
  extern __shared__ float smem[];
  float* xs  = smem;            // MR*66
  float* wsh = smem + MR*66;    // 6144 raw W1(4096)+W2(2048)

  const int tid  = threadIdx.x;
  const int row0 = blockIdx.x * MR;

  for (int idx = tid; idx < MR*64; idx += MR)
    xs[(idx>>6)*66 + (idx&63)] = x[(size_t)row0*64 + idx];
  for (int idx = tid; idx < 6144; idx += MR)
    wsh[idx] = (idx < 4096) ? W1[idx] : W2[idx-4096];
  __syncthreads();

  u64 xp[32];
  {
    const u64* xr = (const u64*)(xs + tid*66);
    #pragma unroll
    for (int k=0;k<32;k++) xp[k] = xr[k];
  }

  float h1f[64];
  #pragma unroll
  for (int j = 0; j < 64; j++){
    const int jj = j % 63;
    const float* wrow = wsh + j*64;
    const u64* wr = (const u64*)wrow;
    u64 a0=0ull,a1=0ull,a2=0ull,a3=0ull;
    #pragma unroll
    for (int k = 0; k < 32; k++){
      if (2*k + 1 <= jj){
        if      ((k&3)==0) fma2(a0, xp[k], wr[k]);
        else if ((k&3)==1) fma2(a1, xp[k], wr[k]);
        else if ((k&3)==2) fma2(a2, xp[k], wr[k]);
        else               fma2(a3, xp[k], wr[k]);
      }
    }
    float2 s0=unpk(a0), s1=unpk(a1), s2=unpk(a2), s3=unpk(a3);
    float s = ((s0.x+s0.y)+(s1.x+s1.y)) + ((s2.x+s2.y)+(s3.x+s3.y));
    if ((jj & 1) == 0) s = fmaf(unpk(xp[jj>>1]).x, wrow[jj], s);
    h1f[j] = fmaxf(s + __ldg(b1 + j), 0.f);
  }

  #pragma unroll
  for (int j = 0; j < 32; j++){
    const float* wrow = wsh + 4096 + j*64;
    float a0=0.f,a1=0.f,a2=0.f,a3=0.f;
    #pragma unroll
    for (int i = 0; i < 63; i++){
      if (i <= j){
        if      ((i&3)==0) a0 = fmaf(h1f[i], wrow[i], a0);
        else if ((i&3)==1) a1 = fmaf(h1f[i], wrow[i], a1);
        else if ((i&3)==2) a2 = fmaf(h1f[i], wrow[i], a2);
        else               a3 = fmaf(h1f[i], wrow[i], a3);
      }
    }
    a0 = fmaf(h1f[63], wrow[63], a0);
    float s = ((a0+a1)+(a2+a3)) + __ldg(b2 + j);
    xs[tid*66 + j] = fmaxf(s, 0.f);
  }
  __syncthreads();
  for (int idx = tid; idx < MR*32; idx += MR)
    g_h2[(size_t)row0*32 + idx] = xs[(idx>>5)*66 + (idx&31)];
}

// ================= spline: projection + RQ spline (Round-12 proven) =================
template<int KM, int CNT>
__device__ __forceinline__ void pvb(float* o, const u64* h2p,
                                    const float* slab, const float* bb, int m0)
{
  #pragma unroll
  for (int mm = 0; mm < CNT; mm++){
    int m = m0 + mm;
    const ulonglong2* W = (const ulonglong2*)(slab + m*32);
    u64 a0 = 0ull, a1 = 0ull;
    #pragma unroll
    for (int k = 0; k < KM; k++){
      ulonglong2 w = W[k];
      fma2(a0, h2p[2*k],   w.x);
      fma2(a1, h2p[2*k+1], w.y);
    }
    float2 s0 = unpk(a0), s1 = unpk(a1);
    o[mm] = s0.x + s0.y + s1.x + s1.y + bb[m];
  }
}

__device__ __forceinline__ void softmax_cum(const float* v, float* cum)
{
  float mx = v[0];
  #pragma unroll
  for (int k=1;k<8;k++) mx = fmaxf(mx, v[k]);
  float ev[8], s = 0.f;
  #pragma unroll
  for (int k=0;k<8;k++){ ev[k] = __expf(v[k]-mx); s += ev[k]; }
  float inv = 1.0f / s;
  cum[0] = -3.f; float c = 0.f;
  #pragma unroll
  for (int k=0;k<7;k++){ c += 1e-3f + 0.992f*(ev[k]*inv); cum[k+1] = fmaf(6.f, c, -3.f); }
  cum[8] = 3.f;
}

__device__ __forceinline__ void rq_eval(const float* cumw, const float* cumh,
                                        const float* der, float xv,
                                        float& yo, float& ldo)
{
  float xc = fminf(fmaxf(xv, -3.f), 3.f);
  bool inside = (xv >= -3.f) && (xv <= 3.f);

  int cnt = 0;
  #pragma unroll
  for (int k=0;k<9;k++) cnt += (xc >= cumw[k] + 1e-6f) ? 1 : 0;
  int bi = cnt - 1; bi = bi < 0 ? 0 : (bi > 7 ? 7 : bi);

  float xk = cumw[0], xk1 = cumw[1], yk = cumh[0], yk1 = cumh[1], dk = der[0], dk1 = der[1];
  #pragma unroll
  for (int k=1;k<8;k++){
    bool m = (bi == k);
    xk  = m ? cumw[k]   : xk;   xk1 = m ? cumw[k+1] : xk1;
    yk  = m ? cumh[k]   : yk;   yk1 = m ? cumh[k+1] : yk1;
    dk  = m ? der[k]    : dk;   dk1 = m ? der[k+1]  : dk1;
  }
  float wk = xk1 - xk, hk = yk1 - yk;
  float invwk = 1.0f / wk;
  float delta = hk * invwk;
  float th  = (xc - xk) * invwk;
  float omt = 1.f - th;
  float tt  = th * omt;
  float th2 = th * th;
  float num = hk * (delta*th2 + dk*tt);
  float den = delta + (dk + dk1 - 2.f*delta) * tt;
  float y   = yk + num / den;
  float dnum = delta*delta * (dk1*th2 + 2.f*delta*tt + dk*omt*omt);
  float ldv  = __logf(dnum) - 2.f*__logf(den);

  yo  = inside ? y   : xv;
  ldo = inside ? ldv : 0.f;
}

template<int KM>
__device__ __forceinline__ void spline_body(const float* h2row, const float* slabs,
                                            const float* b3s, int ds,
                                            const float* xin, float* y2, float& ldacc)
{
  u64 h2p[2*KM];
  {
    const u64* hp = (const u64*)h2row;
    #pragma unroll
    for (int k = 0; k < 2*KM; k++) h2p[k] = hp[k];
  }
  #pragma unroll
  for (int p = 0; p < 2; p++){
    const int c = ds*2 + p;
    const float* slab = slabs + c*768;
    const float* bb   = b3s + c*24;

    float t8[8], cumw[9], cumh[9], der[9];
    pvb<KM,8>(t8, h2p, slab, bb, 0);
    softmax_cum(t8, cumw);
    pvb<KM,8>(t8, h2p, slab, bb, 8);
    softmax_cum(t8, cumh);
    pvb<KM,7>(t8, h2p, slab, bb, 16);
    der[0] = 1.f; der[8] = 1.f;
    #pragma unroll
    for (int k=0;k<7;k++){
      float v = t8[k];
      float sp = fmaxf(v, 0.f) + __logf(1.f + __expf(-fabsf(v)));
      der[k+1] = 1e-3f + sp;
    }

    float yo, ldo;
    rq_eval(cumw, cumh, der, xin[p], yo, ldo);
    y2[p] = yo;
    ldacc += ldo;
  }
}

__global__ __launch_bounds__(256, 3)
void spline_kernel(const float* __restrict__ x,
                   const float* __restrict__ W3, const float* __restrict__ b3,
                   float* __restrict__ out, int B)
{
  __shared__ __align__(16) float h2s[128*34];
  __shared__ __align__(16) float slabs[4*768];
  __shared__ float b3s[96];
  __shared__ __align__(16) float zsm[512];
  __shared__ float lsum[256];

  const int tid  = threadIdx.x;
  const int r    = tid & 127;
  const int ds   = tid >> 7;
  const int row0 = blockIdx.x * 128;
  const int g    = blockIdx.y;
  const int D0   = g * 4;
  const int kmax = (g + 1 < 8) ? (g + 1) : 8;

  // stage h2 tile
  {
    const float2* src = (const float2*)(g_h2 + (size_t)row0*32);
    #pragma unroll
    for (int it = 0; it < 8; it++){
      int idx = tid + it*256;
      int rr = idx >> 4, cc = idx & 15;
      *(float2*)(h2s + rr*34 + cc*2) = src[idx];
    }
  }
  // stage 4 W3 slabs directly from raw W3, applying the MADE mask inline
  #pragma unroll
  for (int it = 0; it < 12; it++){
    int idx = tid + it*256;          // 0..3071
    int dt  = idx / 768;
    int rem = idx - dt*768;
    int m   = rem >> 5, i = rem & 31;
    int d   = D0 + dt;
    float v = 0.f;
    if (m < 23 && i < d) v = __ldg(W3 + (m*64 + d)*32 + i);
    slabs[idx] = v;
  }
  if (tid < 96){
    int dt = tid / 24, m = tid % 24;
    b3s[tid] = (m < 23) ? __ldg(b3 + m*64 + D0 + dt) : 0.f;
  }
  __syncthreads();

  float2 xv2 = *(const float2*)(x + (size_t)(row0 + r)*64 + D0 + ds*2);
  float xin[2] = {xv2.x, xv2.y};
  float y2[2];
  float ldacc = 0.f;
  const float* h2row = h2s + r*34;

  switch (kmax){
    case 1: spline_body<1>(h2row, slabs, b3s, ds, xin, y2, ldacc); break;
    case 2: spline_body<2>(h2row, slabs, b3s, ds, xin, y2, ldacc); break;
    case 3: spline_body<3>(h2row, slabs, b3s, ds, xin, y2, ldacc); break;
    case 4: spline_body<4>(h2row, slabs, b3s, ds, xin, y2, ldacc); break;
    case 5: spline_body<5>(h2row, slabs, b3s, ds, xin, y2, ldacc); break;
    case 6: spline_body<6>(h2row, slabs, b3s, ds, xin, y2, ldacc); break;
    case 7: spline_body<7>(h2row, slabs, b3s, ds, xin, y2, ldacc); break;
    default: spline_body<8>(h2row, slabs, b3s, ds, xin, y2, ldacc); break;
  }

  zsm[r*4 + ds*2 + 0] = y2[0];
  zsm[r*4 + ds*2 + 1] = y2[1];
  lsum[tid] = ldacc;
  __syncthreads();

  if (tid < 128){
    float4 v = *(const float4*)(zsm + tid*4);
    *(float4*)(out + (size_t)(row0 + tid)*64 + D0) = v;
    atomicAdd(out + (size_t)B*64 + row0 + tid, lsum[tid] + lsum[tid + 128]);
  }
}

// ================= launch =================
extern "C" void kernel_launch(void* const* d_in, const int* in_sizes, int n_in,
                              void* d_out, int out_size)
{
  const float* x  = (const float*)d_in[0];
  const float* W1 = (const float*)d_in[1];
  const float* b1 = (const float*)d_in[2];
  const float* W2 = (const float*)d_in[3];
  const float* b2 = (const float*)d_in[4];
  const float* W3 = (const float*)d_in[5];
  const float* b3 = (const float*)d_in[6];
  float* out = (float*)d_out;

  int B = in_sizes[0] / 64;
  int smemA = (MR*66 + 6144) * (int)sizeof(float);   // 41472

  cudaFuncSetAttribute(made_kernel,
                       cudaFuncAttributeMaxDynamicSharedMemorySize, smemA);

  // zero the log-det accumulator region (graph-capturable async memset)
  cudaMemsetAsync(out + (size_t)B*64, 0, (size_t)B * sizeof(float));

  made_kernel<<<B/MR, MR, smemA>>>(x, W1, b1, W2, b2, B);
  spline_kernel<<<dim3(B/128, 16), 256>>>(x, W3, b3, out, B);
}

// round 16
// speedup vs baseline: 1.0537x; 1.0142x over previous
#include <cuda_runtime.h>

typedef unsigned long long u64;

__device__ float g_h2[32768 * 32];

__device__ __forceinline__ void fma2(u64 &acc, u64 a, u64 b){
  asm("fma.rn.f32x2 %0, %1, %2, %0;" : "+l"(acc) : "l"(a), "l"(b));
}
__device__ __forceinline__ float2 unpk(u64 v){
  float2 f; asm("mov.b64 {%0,%1}, %2;" : "=f"(f.x), "=f"(f.y) : "l"(v)); return f;
}

// ================= MADE (frozen, Round-4 proven) =================
#define MR 64
__global__ __launch_bounds__(MR)
void made_kernel(const float* __restrict__ x,
                 const float* __restrict__ W1, const float* __restrict__ b1,
                 const float* __restrict__ W2, const float* __restrict__ b2,
                 int B)
{
  extern __shared__ float smem[];
  float* xs  = smem;            // MR*66
  float* wsh = smem + MR*66;    // 6144 raw W1(4096)+W2(2048)

  const int tid  = threadIdx.x;
  const int row0 = blockIdx.x * MR;

  for (int idx = tid; idx < MR*64; idx += MR)
    xs[(idx>>6)*66 + (idx&63)] = x[(size_t)row0*64 + idx];
  for (int idx = tid; idx < 6144; idx += MR)
    wsh[idx] = (idx < 4096) ? W1[idx] : W2[idx-4096];
  __syncthreads();

  u64 xp[32];
  {
    const u64* xr = (const u64*)(xs + tid*66);
    #pragma unroll
    for (int k=0;k<32;k++) xp[k] = xr[k];
  }

  float h1f[64];
  #pragma unroll
  for (int j = 0; j < 64; j++){
    const int jj = j % 63;
    const float* wrow = wsh + j*64;
    const u64* wr = (const u64*)wrow;
    u64 a0=0ull,a1=0ull,a2=0ull,a3=0ull;
    #pragma unroll
    for (int k = 0; k < 32; k++){
      if (2*k + 1 <= jj){
        if      ((k&3)==0) fma2(a0, xp[k], wr[k]);
        else if ((k&3)==1) fma2(a1, xp[k], wr[k]);
        else if ((k&3)==2) fma2(a2, xp[k], wr[k]);
        else               fma2(a3, xp[k], wr[k]);
      }
    }
    float2 s0=unpk(a0), s1=unpk(a1), s2=unpk(a2), s3=unpk(a3);
    float s = ((s0.x+s0.y)+(s1.x+s1.y)) + ((s2.x+s2.y)+(s3.x+s3.y));
    if ((jj & 1) == 0) s = fmaf(unpk(xp[jj>>1]).x, wrow[jj], s);
    h1f[j] = fmaxf(s + __ldg(b1 + j), 0.f);
  }

  #pragma unroll
  for (int j = 0; j < 32; j++){
    const float* wrow = wsh + 4096 + j*64;
    float a0=0.f,a1=0.f,a2=0.f,a3=0.f;
    #pragma unroll
    for (int i = 0; i < 63; i++){
      if (i <= j){
        if      ((i&3)==0) a0 = fmaf(h1f[i], wrow[i], a0);
        else if ((i&3)==1) a1 = fmaf(h1f[i], wrow[i], a1);
        else if ((i&3)==2) a2 = fmaf(h1f[i], wrow[i], a2);
        else               a3 = fmaf(h1f[i], wrow[i], a3);
      }
    }
    a0 = fmaf(h1f[63], wrow[63], a0);
    float s = ((a0+a1)+(a2+a3)) + __ldg(b2 + j);
    xs[tid*66 + j] = fmaxf(s, 0.f);
  }
  __syncthreads();
  for (int idx = tid; idx < MR*32; idx += MR)
    g_h2[(size_t)row0*32 + idx] = xs[(idx>>5)*66 + (idx&31)];
}

// ================= shared spline math =================
template<int KM, int CNT>
__device__ __forceinline__ void pvb(float* o, const u64* h2p,
                                    const float* slab, const float* bb, int m0)
{
  #pragma unroll
  for (int mm = 0; mm < CNT; mm++){
    int m = m0 + mm;
    const ulonglong2* W = (const ulonglong2*)(slab + m*32);
    u64 a0 = 0ull, a1 = 0ull;
    #pragma unroll
    for (int k = 0; k < KM; k++){
      ulonglong2 w = W[k];
      fma2(a0, h2p[2*k],   w.x);
      fma2(a1, h2p[2*k+1], w.y);
    }
    float2 s0 = unpk(a0), s1 = unpk(a1);
    o[mm] = s0.x + s0.y + s1.x + s1.y + bb[m];
  }
}

__device__ __forceinline__ void softmax_cum(const float* v, float* cum)
{
  float mx = v[0];
  #pragma unroll
  for (int k=1;k<8;k++) mx = fmaxf(mx, v[k]);
  float ev[8], s = 0.f;
  #pragma unroll
  for (int k=0;k<8;k++){ ev[k] = __expf(v[k]-mx); s += ev[k]; }
  float inv = 1.0f / s;
  cum[0] = -3.f; float c = 0.f;
  #pragma unroll
  for (int k=0;k<7;k++){ c += 1e-3f + 0.992f*(ev[k]*inv); cum[k+1] = fmaf(6.f, c, -3.f); }
  cum[8] = 3.f;
}

__device__ __forceinline__ void rq_eval(const float* cumw, const float* cumh,
                                        const float* der, float xv,
                                        float& yo, float& ldo)
{
  float xc = fminf(fmaxf(xv, -3.f), 3.f);
  bool inside = (xv >= -3.f) && (xv <= 3.f);

  int cnt = 0;
  #pragma unroll
  for (int k=0;k<9;k++) cnt += (xc >= cumw[k] + 1e-6f) ? 1 : 0;
  int bi = cnt - 1; bi = bi < 0 ? 0 : (bi > 7 ? 7 : bi);

  float xk = cumw[0], xk1 = cumw[1], yk = cumh[0], yk1 = cumh[1], dk = der[0], dk1 = der[1];
  #pragma unroll
  for (int k=1;k<8;k++){
    bool m = (bi == k);
    xk  = m ? cumw[k]   : xk;   xk1 = m ? cumw[k+1] : xk1;
    yk  = m ? cumh[k]   : yk;   yk1 = m ? cumh[k+1] : yk1;
    dk  = m ? der[k]    : dk;   dk1 = m ? der[k+1]  : dk1;
  }
  float wk = xk1 - xk, hk = yk1 - yk;
  float invwk = 1.0f / wk;
  float delta = hk * invwk;
  float th  = (xc - xk) * invwk;
  float omt = 1.f - th;
  float tt  = th * omt;
  float th2 = th * th;
  float num = hk * (delta*th2 + dk*tt);
  float den = delta + (dk + dk1 - 2.f*delta) * tt;
  float y   = yk + num / den;
  float dnum = delta*delta * (dk1*th2 + 2.f*delta*tt + dk*omt*omt);
  float ldv  = __logf(dnum) - 2.f*__logf(den);

  yo  = inside ? y   : xv;
  ldo = inside ? ldv : 0.f;
}

// ================= spline_lo: g=0..6 (KM 1..7), R12 single-row body =================
template<int KM>
__device__ __forceinline__ void spline_body(const float* h2row, const float* slabs,
                                            const float* b3s, int ds,
                                            const float* xin, float* y2, float& ldacc)
{
  u64 h2p[2*KM];
  {
    const u64* hp = (const u64*)h2row;
    #pragma unroll
    for (int k = 0; k < 2*KM; k++) h2p[k] = hp[k];
  }
  #pragma unroll
  for (int p = 0; p < 2; p++){
    const int c = ds*2 + p;
    const float* slab = slabs + c*768;
    const float* bb   = b3s + c*24;

    float t8[8], cumw[9], cumh[9], der[9];
    pvb<KM,8>(t8, h2p, slab, bb, 0);
    softmax_cum(t8, cumw);
    pvb<KM,8>(t8, h2p, slab, bb, 8);
    softmax_cum(t8, cumh);
    pvb<KM,7>(t8, h2p, slab, bb, 16);
    der[0] = 1.f; der[8] = 1.f;
    #pragma unroll
    for (int k=0;k<7;k++){
      float v = t8[k];
      float sp = fmaxf(v, 0.f) + __logf(1.f + __expf(-fabsf(v)));
      der[k+1] = 1e-3f + sp;
    }

    float yo, ldo;
    rq_eval(cumw, cumh, der, xin[p], yo, ldo);
    y2[p] = yo;
    ldacc += ldo;
  }
}

__global__ __launch_bounds__(256, 3)
void spline_lo(const float* __restrict__ x,
               const float* __restrict__ W3, const float* __restrict__ b3,
               float* __restrict__ out, int B)
{
  __shared__ __align__(16) float h2s[128*34];
  __shared__ __align__(16) float slabs[4*768];
  __shared__ float b3s[96];
  __shared__ __align__(16) float zsm[512];
  __shared__ float lsum[256];

  const int tid  = threadIdx.x;
  const int r    = tid & 127;
  const int ds   = tid >> 7;
  const int row0 = blockIdx.x * 128;
  const int g    = blockIdx.y;          // 0..6
  const int D0   = g * 4;
  const int kmax = g + 1;               // 1..7

  {
    const float2* src = (const float2*)(g_h2 + (size_t)row0*32);
    #pragma unroll
    for (int it = 0; it < 8; it++){
      int idx = tid + it*256;
      int rr = idx >> 4, cc = idx & 15;
      *(float2*)(h2s + rr*34 + cc*2) = src[idx];
    }
  }
  #pragma unroll
  for (int it = 0; it < 12; it++){
    int idx = tid + it*256;
    int dt  = idx / 768;
    int rem = idx - dt*768;
    int m   = rem >> 5, i = rem & 31;
    int d   = D0 + dt;
    float v = 0.f;
    if (m < 23 && i < d) v = __ldg(W3 + (m*64 + d)*32 + i);
    slabs[idx] = v;
  }
  if (tid < 96){
    int dt = tid / 24, m = tid % 24;
    b3s[tid] = (m < 23) ? __ldg(b3 + m*64 + D0 + dt) : 0.f;
  }
  __syncthreads();

  float2 xv2 = *(const float2*)(x + (size_t)(row0 + r)*64 + D0 + ds*2);
  float xin[2] = {xv2.x, xv2.y};
  float y2[2];
  float ldacc = 0.f;
  const float* h2row = h2s + r*34;

  switch (kmax){
    case 1: spline_body<1>(h2row, slabs, b3s, ds, xin, y2, ldacc); break;
    case 2: spline_body<2>(h2row, slabs, b3s, ds, xin, y2, ldacc); break;
    case 3: spline_body<3>(h2row, slabs, b3s, ds, xin, y2, ldacc); break;
    case 4: spline_body<4>(h2row, slabs, b3s, ds, xin, y2, ldacc); break;
    case 5: spline_body<5>(h2row, slabs, b3s, ds, xin, y2, ldacc); break;
    case 6: spline_body<6>(h2row, slabs, b3s, ds, xin, y2, ldacc); break;
    default: spline_body<7>(h2row, slabs, b3s, ds, xin, y2, ldacc); break;
  }

  zsm[r*4 + ds*2 + 0] = y2[0];
  zsm[r*4 + ds*2 + 1] = y2[1];
  lsum[tid] = ldacc;
  __syncthreads();

  if (tid < 128){
    float4 v = *(const float4*)(zsm + tid*4);
    *(float4*)(out + (size_t)(row0 + tid)*64 + D0) = v;
    atomicAdd(out + (size_t)B*64 + row0 + tid, lsum[tid] + lsum[tid + 128]);
  }
}

// ================= spline_hi: g=7..15 (KM=8), R13 row-pair body =================
__device__ __forceinline__ void pvb2_8(float* oA, float* oB,
                                       const u64* hA, const u64* hB,
                                       const float* slab, const float* bb,
                                       int m0, int cntm)
{
  #pragma unroll
  for (int mm = 0; mm < 8; mm++){
    if (mm < cntm){
      int m = m0 + mm;
      const ulonglong2* W = (const ulonglong2*)(slab + m*32);
      u64 aA0 = 0ull, aA1 = 0ull, aB0 = 0ull, aB1 = 0ull;
      #pragma unroll
      for (int k = 0; k < 8; k++){
        ulonglong2 w = W[k];                // one broadcast LDS.128 feeds 4 FFMA2
        fma2(aA0, hA[2*k],   w.x);
        fma2(aA1, hA[2*k+1], w.y);
        fma2(aB0, hB[2*k],   w.x);
        fma2(aB1, hB[2*k+1], w.y);
      }
      float2 sA0 = unpk(aA0), sA1 = unpk(aA1);
      float2 sB0 = unpk(aB0), sB1 = unpk(aB1);
      float b = bb[m];
      oA[mm] = sA0.x + sA0.y + sA1.x + sA1.y + b;
      oB[mm] = sB0.x + sB0.y + sB1.x + sB1.y + b;
    }
  }
}

__global__ __launch_bounds__(256, 2)
void spline_hi(const float* __restrict__ x,
               const float* __restrict__ W3, const float* __restrict__ b3,
               float* __restrict__ out, int B)
{
  __shared__ __align__(16) float h2s[128*34];
  __shared__ __align__(16) float slabs[4*768];
  __shared__ float b3s[96];
  __shared__ __align__(16) float zsm[512];
  __shared__ float lsum[512];

  const int tid  = threadIdx.x;
  const int rp   = tid & 63;            // rows rp and rp+64
  const int c    = tid >> 6;            // 0..3
  const int row0 = blockIdx.x * 128;
  const int g    = blockIdx.y + 7;      // 7..15
  const int D0   = g * 4;

  {
    const float2* src = (const float2*)(g_h2 + (size_t)row0*32);
    #pragma unroll
    for (int it = 0; it < 8; it++){
      int idx = tid + it*256;
      int rr = idx >> 4, cc = idx & 15;
      *(float2*)(h2s + rr*34 + cc*2) = src[idx];
    }
  }
  #pragma unroll
  for (int it = 0; it < 12; it++){
    int idx = tid + it*256;
    int dt  = idx / 768;
    int rem = idx - dt*768;
    int m   = rem >> 5, i = rem & 31;
    int d   = D0 + dt;
    float v = 0.f;
    if (m < 23 && i < d) v = __ldg(W3 + (m*64 + d)*32 + i);
    slabs[idx] = v;
  }
  if (tid < 96){
    int dt = tid / 24, m = tid % 24;
    b3s[tid] = (m < 23) ? __ldg(b3 + m*64 + D0 + dt) : 0.f;
  }
  __syncthreads();

  const float* slab = slabs + c*768;
  const float* bb   = b3s + c*24;

  u64 hA[16], hB[16];
  {
    const u64* pa = (const u64*)(h2s + rp*34);
    const u64* pb = (const u64*)(h2s + (rp + 64)*34);
    #pragma unroll
    for (int k = 0; k < 16; k++){ hA[k] = pa[k]; hB[k] = pb[k]; }
  }

  float xA = x[(size_t)(row0 + rp)*64      + D0 + c];
  float xB = x[(size_t)(row0 + rp + 64)*64 + D0 + c];

  float tA[8], tB[8];
  float cwA[9], cwB[9], chA[9], chB[9], derA[9], derB[9];

  pvb2_8(tA, tB, hA, hB, slab, bb, 0, 8);
  softmax_cum(tA, cwA);
  softmax_cum(tB, cwB);

  pvb2_8(tA, tB, hA, hB, slab, bb, 8, 8);
  softmax_cum(tA, chA);
  softmax_cum(tB, chB);

  pvb2_8(tA, tB, hA, hB, slab, bb, 16, 7);
  derA[0] = 1.f; derA[8] = 1.f;
  derB[0] = 1.f; derB[8] = 1.f;
  #pragma unroll
  for (int k=0;k<7;k++){
    float vA = tA[k], vB = tB[k];
    derA[k+1] = 1e-3f + fmaxf(vA, 0.f) + __logf(1.f + __expf(-fabsf(vA)));
    derB[k+1] = 1e-3f + fmaxf(vB, 0.f) + __logf(1.f + __expf(-fabsf(vB)));
  }

  float yA, ldA, yB, ldB;
  rq_eval(cwA, chA, derA, xA, yA, ldA);
  rq_eval(cwB, chB, derB, xB, yB, ldB);

  zsm[rp*4 + c]        = yA;
  zsm[(rp + 64)*4 + c] = yB;
  lsum[c*128 + rp]      = ldA;
  lsum[c*128 + rp + 64] = ldB;
  __syncthreads();

  if (tid < 128){
    float4 v = *(const float4*)(zsm + tid*4);
    *(float4*)(out + (size_t)(row0 + tid)*64 + D0) = v;
    float l = (lsum[tid] + lsum[128 + tid]) + (lsum[256 + tid] + lsum[384 + tid]);
    atomicAdd(out + (size_t)B*64 + row0 + tid, l);
  }
}

// ================= launch =================
extern "C" void kernel_launch(void* const* d_in, const int* in_sizes, int n_in,
                              void* d_out, int out_size)
{
  const float* x  = (const float*)d_in[0];
  const float* W1 = (const float*)d_in[1];
  const float* b1 = (const float*)d_in[2];
  const float* W2 = (const float*)d_in[3];
  const float* b2 = (const float*)d_in[4];
  const float* W3 = (const float*)d_in[5];
  const float* b3 = (const float*)d_in[6];
  float* out = (float*)d_out;

  int B = in_sizes[0] / 64;
  int smemA = (MR*66 + 6144) * (int)sizeof(float);   // 41472

  cudaFuncSetAttribute(made_kernel,
                       cudaFuncAttributeMaxDynamicSharedMemorySize, smemA);

  // zero the log-det accumulator region (graph-capturable async memset)
  cudaMemsetAsync(out + (size_t)B*64, 0, (size_t)B * sizeof(float));

  made_kernel<<<B/MR, MR, smemA>>>(x, W1, b1, W2, b2, B);
  spline_hi<<<dim3(B/128, 9), 256>>>(x, W3, b3, out, B);   // bigger kernel first
  spline_lo<<<dim3(B/128, 7), 256>>>(x, W3, b3, out, B);   // fills hi's tail
}

// round 17
// speedup vs baseline: 1.0571x; 1.0032x over previous
#include <cuda_runtime.h>

typedef unsigned long long u64;

__device__ float g_h2[32768 * 32];

__device__ __forceinline__ void fma2(u64 &acc, u64 a, u64 b){
  asm("fma.rn.f32x2 %0, %1, %2, %0;" : "+l"(acc) : "l"(a), "l"(b));
}
__device__ __forceinline__ float2 unpk(u64 v){
  float2 f; asm("mov.b64 {%0,%1}, %2;" : "=f"(f.x), "=f"(f.y) : "l"(v)); return f;
}

// ================= MADE: dead h1 columns (32..62) eliminated =================
// m2[j2,i] = (i%63 <= j2), j2<=31  =>  h1 cols 32..62 never used.
// h1[63] has degree 1: only i=0 contributes.
#define MR 64
__global__ __launch_bounds__(MR)
void made_kernel(const float* __restrict__ x,
                 const float* __restrict__ W1, const float* __restrict__ b1,
                 const float* __restrict__ W2, const float* __restrict__ b2,
                 int B)
{
  extern __shared__ float smem[];
  float* xs  = smem;            // MR*66
  float* wsh = smem + MR*66;    // 6144 raw W1(4096)+W2(2048)

  const int tid  = threadIdx.x;
  const int row0 = blockIdx.x * MR;

  for (int idx = tid; idx < MR*64; idx += MR)
    xs[(idx>>6)*66 + (idx&63)] = x[(size_t)row0*64 + idx];
  for (int idx = tid; idx < 6144; idx += MR)
    wsh[idx] = (idx < 4096) ? W1[idx] : W2[idx-4096];
  __syncthreads();

  u64 xp[32];
  {
    const u64* xr = (const u64*)(xs + tid*66);
    #pragma unroll
    for (int k=0;k<32;k++) xp[k] = xr[k];
  }

  // ---- phase 1: only live h1 columns j in {0..31, 63} ----
  float h1f[32];
  #pragma unroll
  for (int j = 0; j < 32; j++){
    const int jj = j;                            // j%63 = j for j<32
    const float* wrow = wsh + j*64;
    const u64* wr = (const u64*)wrow;
    u64 a0=0ull,a1=0ull,a2=0ull,a3=0ull;
    #pragma unroll
    for (int k = 0; k < 16; k++){                // i <= 31 -> chunks k <= 15
      if (2*k + 1 <= jj){
        if      ((k&3)==0) fma2(a0, xp[k], wr[k]);
        else if ((k&3)==1) fma2(a1, xp[k], wr[k]);
        else if ((k&3)==2) fma2(a2, xp[k], wr[k]);
        else               fma2(a3, xp[k], wr[k]);
      }
    }
    float2 s0=unpk(a0), s1=unpk(a1), s2=unpk(a2), s3=unpk(a3);
    float s = ((s0.x+s0.y)+(s1.x+s1.y)) + ((s2.x+s2.y)+(s3.x+s3.y));
    if ((jj & 1) == 0) s = fmaf(unpk(xp[jj>>1]).x, wrow[jj], s);  // straggler i=jj
    h1f[j] = fmaxf(s + __ldg(b1 + j), 0.f);
  }
  // h1[63]: degree wraps to 1 -> only i=0
  const float h63 = fmaxf(fmaf(unpk(xp[0]).x, wsh[63*64 + 0], __ldg(b1 + 63)), 0.f);

  // ---- phase 2: h2(j2) over live i in {0..j2, 63} ----
  #pragma unroll
  for (int j = 0; j < 32; j++){
    const float* wrow = wsh + 4096 + j*64;
    float a0=0.f,a1=0.f,a2=0.f,a3=0.f;
    #pragma unroll
    for (int i = 0; i < 32; i++){
      if (i <= j){                               // compile-time mask
        if      ((i&3)==0) a0 = fmaf(h1f[i], wrow[i], a0);
        else if ((i&3)==1) a1 = fmaf(h1f[i], wrow[i], a1);
        else if ((i&3)==2) a2 = fmaf(h1f[i], wrow[i], a2);
        else               a3 = fmaf(h1f[i], wrow[i], a3);
      }
    }
    a0 = fmaf(h63, wrow[63], a0);                // i=63 always in-mask
    float s = ((a0+a1)+(a2+a3)) + __ldg(b2 + j);
    xs[tid*66 + j] = fmaxf(s, 0.f);
  }
  __syncthreads();
  for (int idx = tid; idx < MR*32; idx += MR)
    g_h2[(size_t)row0*32 + idx] = xs[(idx>>5)*66 + (idx&31)];
}

// ================= shared spline math =================
template<int KM, int CNT>
__device__ __forceinline__ void pvb(float* o, const u64* h2p,
                                    const float* slab, const float* bb, int m0)
{
  #pragma unroll
  for (int mm = 0; mm < CNT; mm++){
    int m = m0 + mm;
    const ulonglong2* W = (const ulonglong2*)(slab + m*32);
    u64 a0 = 0ull, a1 = 0ull;
    #pragma unroll
    for (int k = 0; k < KM; k++){
      ulonglong2 w = W[k];
      fma2(a0, h2p[2*k],   w.x);
      fma2(a1, h2p[2*k+1], w.y);
    }
    float2 s0 = unpk(a0), s1 = unpk(a1);
    o[mm] = s0.x + s0.y + s1.x + s1.y + bb[m];
  }
}

__device__ __forceinline__ void softmax_cum(const float* v, float* cum)
{
  float mx = v[0];
  #pragma unroll
  for (int k=1;k<8;k++) mx = fmaxf(mx, v[k]);
  float ev[8], s = 0.f;
  #pragma unroll
  for (int k=0;k<8;k++){ ev[k] = __expf(v[k]-mx); s += ev[k]; }
  float inv = 1.0f / s;
  cum[0] = -3.f; float c = 0.f;
  #pragma unroll
  for (int k=0;k<7;k++){ c += 1e-3f + 0.992f*(ev[k]*inv); cum[k+1] = fmaf(6.f, c, -3.f); }
  cum[8] = 3.f;
}

__device__ __forceinline__ void rq_eval(const float* cumw, const float* cumh,
                                        const float* der, float xv,
                                        float& yo, float& ldo)
{
  float xc = fminf(fmaxf(xv, -3.f), 3.f);
  bool inside = (xv >= -3.f) && (xv <= 3.f);

  int cnt = 0;
  #pragma unroll
  for (int k=0;k<9;k++) cnt += (xc >= cumw[k] + 1e-6f) ? 1 : 0;
  int bi = cnt - 1; bi = bi < 0 ? 0 : (bi > 7 ? 7 : bi);

  float xk = cumw[0], xk1 = cumw[1], yk = cumh[0], yk1 = cumh[1], dk = der[0], dk1 = der[1];
  #pragma unroll
  for (int k=1;k<8;k++){
    bool m = (bi == k);
    xk  = m ? cumw[k]   : xk;   xk1 = m ? cumw[k+1] : xk1;
    yk  = m ? cumh[k]   : yk;   yk1 = m ? cumh[k+1] : yk1;
    dk  = m ? der[k]    : dk;   dk1 = m ? der[k+1]  : dk1;
  }
  float wk = xk1 - xk, hk = yk1 - yk;
  float invwk = 1.0f / wk;
  float delta = hk * invwk;
  float th  = (xc - xk) * invwk;
  float omt = 1.f - th;
  float tt  = th * omt;
  float th2 = th * th;
  float num = hk * (delta*th2 + dk*tt);
  float den = delta + (dk + dk1 - 2.f*delta) * tt;
  float y   = yk + num / den;
  float dnum = delta*delta * (dk1*th2 + 2.f*delta*tt + dk*omt*omt);
  float ldv  = __logf(dnum) - 2.f*__logf(den);

  yo  = inside ? y   : xv;
  ldo = inside ? ldv : 0.f;
}

// ================= spline_lo: g=0..6 (KM 1..7), R12 single-row body =================
template<int KM>
__device__ __forceinline__ void spline_body(const float* h2row, const float* slabs,
                                            const float* b3s, int ds,
                                            const float* xin, float* y2, float& ldacc)
{
  u64 h2p[2*KM];
  {
    const u64* hp = (const u64*)h2row;
    #pragma unroll
    for (int k = 0; k < 2*KM; k++) h2p[k] = hp[k];
  }
  #pragma unroll
  for (int p = 0; p < 2; p++){
    const int c = ds*2 + p;
    const float* slab = slabs + c*768;
    const float* bb   = b3s + c*24;

    float t8[8], cumw[9], cumh[9], der[9];
    pvb<KM,8>(t8, h2p, slab, bb, 0);
    softmax_cum(t8, cumw);
    pvb<KM,8>(t8, h2p, slab, bb, 8);
    softmax_cum(t8, cumh);
    pvb<KM,7>(t8, h2p, slab, bb, 16);
    der[0] = 1.f; der[8] = 1.f;
    #pragma unroll
    for (int k=0;k<7;k++){
      float v = t8[k];
      float sp = fmaxf(v, 0.f) + __logf(1.f + __expf(-fabsf(v)));
      der[k+1] = 1e-3f + sp;
    }

    float yo, ldo;
    rq_eval(cumw, cumh, der, xin[p], yo, ldo);
    y2[p] = yo;
    ldacc += ldo;
  }
}

__global__ __launch_bounds__(256, 3)
void spline_lo(const float* __restrict__ x,
               const float* __restrict__ W3, const float* __restrict__ b3,
               float* __restrict__ out, int B)
{
  __shared__ __align__(16) float h2s[128*34];
  __shared__ __align__(16) float slabs[4*768];
  __shared__ float b3s[96];
  __shared__ __align__(16) float zsm[512];
  __shared__ float lsum[256];

  const int tid  = threadIdx.x;
  const int r    = tid & 127;
  const int ds   = tid >> 7;
  const int row0 = blockIdx.x * 128;
  const int g    = blockIdx.y;          // 0..6
  const int D0   = g * 4;
  const int kmax = g + 1;               // 1..7

  {
    const float2* src = (const float2*)(g_h2 + (size_t)row0*32);
    #pragma unroll
    for (int it = 0; it < 8; it++){
      int idx = tid + it*256;
      int rr = idx >> 4, cc = idx & 15;
      *(float2*)(h2s + rr*34 + cc*2) = src[idx];
    }
  }
  #pragma unroll
  for (int it = 0; it < 12; it++){
    int idx = tid + it*256;
    int dt  = idx / 768;
    int rem = idx - dt*768;
    int m   = rem >> 5, i = rem & 31;
    int d   = D0 + dt;
    float v = 0.f;
    if (m < 23 && i < d) v = __ldg(W3 + (m*64 + d)*32 + i);
    slabs[idx] = v;
  }
  if (tid < 96){
    int dt = tid / 24, m = tid % 24;
    b3s[tid] = (m < 23) ? __ldg(b3 + m*64 + D0 + dt) : 0.f;
  }
  __syncthreads();

  float2 xv2 = *(const float2*)(x + (size_t)(row0 + r)*64 + D0 + ds*2);
  float xin[2] = {xv2.x, xv2.y};
  float y2[2];
  float ldacc = 0.f;
  const float* h2row = h2s + r*34;

  switch (kmax){
    case 1: spline_body<1>(h2row, slabs, b3s, ds, xin, y2, ldacc); break;
    case 2: spline_body<2>(h2row, slabs, b3s, ds, xin, y2, ldacc); break;
    case 3: spline_body<3>(h2row, slabs, b3s, ds, xin, y2, ldacc); break;
    case 4: spline_body<4>(h2row, slabs, b3s, ds, xin, y2, ldacc); break;
    case 5: spline_body<5>(h2row, slabs, b3s, ds, xin, y2, ldacc); break;
    case 6: spline_body<6>(h2row, slabs, b3s, ds, xin, y2, ldacc); break;
    default: spline_body<7>(h2row, slabs, b3s, ds, xin, y2, ldacc); break;
  }

  zsm[r*4 + ds*2 + 0] = y2[0];
  zsm[r*4 + ds*2 + 1] = y2[1];
  lsum[tid] = ldacc;
  __syncthreads();

  if (tid < 128){
    float4 v = *(const float4*)(zsm + tid*4);
    *(float4*)(out + (size_t)(row0 + tid)*64 + D0) = v;
    atomicAdd(out + (size_t)B*64 + row0 + tid, lsum[tid] + lsum[tid + 128]);
  }
}

// ================= spline_hi: g=7..15 (KM=8), R13 row-pair body =================
__device__ __forceinline__ void pvb2_8(float* oA, float* oB,
                                       const u64* hA, const u64* hB,
                                       const float* slab, const float* bb,
                                       int m0, int cntm)
{
  #pragma unroll
  for (int mm = 0; mm < 8; mm++){
    if (mm < cntm){
      int m = m0 + mm;
      const ulonglong2* W = (const ulonglong2*)(slab + m*32);
      u64 aA0 = 0ull, aA1 = 0ull, aB0 = 0ull, aB1 = 0ull;
      #pragma unroll
      for (int k = 0; k < 8; k++){
        ulonglong2 w = W[k];                // one broadcast LDS.128 feeds 4 FFMA2
        fma2(aA0, hA[2*k],   w.x);
        fma2(aA1, hA[2*k+1], w.y);
        fma2(aB0, hB[2*k],   w.x);
        fma2(aB1, hB[2*k+1], w.y);
      }
      float2 sA0 = unpk(aA0), sA1 = unpk(aA1);
      float2 sB0 = unpk(aB0), sB1 = unpk(aB1);
      float b = bb[m];
      oA[mm] = sA0.x + sA0.y + sA1.x + sA1.y + b;
      oB[mm] = sB0.x + sB0.y + sB1.x + sB1.y + b;
    }
  }
}

__global__ __launch_bounds__(256, 2)
void spline_hi(const float* __restrict__ x,
               const float* __restrict__ W3, const float* __restrict__ b3,
               float* __restrict__ out, int B)
{
  __shared__ __align__(16) float h2s[128*34];
  __shared__ __align__(16) float slabs[4*768];
  __shared__ float b3s[96];
  __shared__ __align__(16) float zsm[512];
  __shared__ float lsum[512];

  const int tid  = threadIdx.x;
  const int rp   = tid & 63;            // rows rp and rp+64
  const int c    = tid >> 6;            // 0..3
  const int row0 = blockIdx.x * 128;
  const int g    = blockIdx.y + 7;      // 7..15
  const int D0   = g * 4;

  {
    const float2* src = (const float2*)(g_h2 + (size_t)row0*32);
    #pragma unroll
    for (int it = 0; it < 8; it++){
      int idx = tid + it*256;
      int rr = idx >> 4, cc = idx & 15;
      *(float2*)(h2s + rr*34 + cc*2) = src[idx];
    }
  }
  #pragma unroll
  for (int it = 0; it < 12; it++){
    int idx = tid + it*256;
    int dt  = idx / 768;
    int rem = idx - dt*768;
    int m   = rem >> 5, i = rem & 31;
    int d   = D0 + dt;
    float v = 0.f;
    if (m < 23 && i < d) v = __ldg(W3 + (m*64 + d)*32 + i);
    slabs[idx] = v;
  }
  if (tid < 96){
    int dt = tid / 24, m = tid % 24;
    b3s[tid] = (m < 23) ? __ldg(b3 + m*64 + D0 + dt) : 0.f;
  }
  __syncthreads();

  const float* slab = slabs + c*768;
  const float* bb   = b3s + c*24;

  u64 hA[16], hB[16];
  {
    const u64* pa = (const u64*)(h2s + rp*34);
    const u64* pb = (const u64*)(h2s + (rp + 64)*34);
    #pragma unroll
    for (int k = 0; k < 16; k++){ hA[k] = pa[k]; hB[k] = pb[k]; }
  }

  float xA = x[(size_t)(row0 + rp)*64      + D0 + c];
  float xB = x[(size_t)(row0 + rp + 64)*64 + D0 + c];

  float tA[8], tB[8];
  float cwA[9], cwB[9], chA[9], chB[9], derA[9], derB[9];

  pvb2_8(tA, tB, hA, hB, slab, bb, 0, 8);
  softmax_cum(tA, cwA);
  softmax_cum(tB, cwB);

  pvb2_8(tA, tB, hA, hB, slab, bb, 8, 8);
  softmax_cum(tA, chA);
  softmax_cum(tB, chB);

  pvb2_8(tA, tB, hA, hB, slab, bb, 16, 7);
  derA[0] = 1.f; derA[8] = 1.f;
  derB[0] = 1.f; derB[8] = 1.f;
  #pragma unroll
  for (int k=0;k<7;k++){
    float vA = tA[k], vB = tB[k];
    derA[k+1] = 1e-3f + fmaxf(vA, 0.f) + __logf(1.f + __expf(-fabsf(vA)));
    derB[k+1] = 1e-3f + fmaxf(vB, 0.f) + __logf(1.f + __expf(-fabsf(vB)));
  }

  float yA, ldA, yB, ldB;
  rq_eval(cwA, chA, derA, xA, yA, ldA);
  rq_eval(cwB, chB, derB, xB, yB, ldB);

  zsm[rp*4 + c]        = yA;
  zsm[(rp + 64)*4 + c] = yB;
  lsum[c*128 + rp]      = ldA;
  lsum[c*128 + rp + 64] = ldB;
  __syncthreads();

  if (tid < 128){
    float4 v = *(const float4*)(zsm + tid*4);
    *(float4*)(out + (size_t)(row0 + tid)*64 + D0) = v;
    float l = (lsum[tid] + lsum[128 + tid]) + (lsum[256 + tid] + lsum[384 + tid]);
    atomicAdd(out + (size_t)B*64 + row0 + tid, l);
  }
}

// ================= launch =================
extern "C" void kernel_launch(void* const* d_in, const int* in_sizes, int n_in,
                              void* d_out, int out_size)
{
  const float* x  = (const float*)d_in[0];
  const float* W1 = (const float*)d_in[1];
  const float* b1 = (const float*)d_in[2];
  const float* W2 = (const float*)d_in[3];
  const float* b2 = (const float*)d_in[4];
  const float* W3 = (const float*)d_in[5];
  const float* b3 = (const float*)d_in[6];
  float* out = (float*)d_out;

  int B = in_sizes[0] / 64;
  int smemA = (MR*66 + 6144) * (int)sizeof(float);   // 41472

  cudaFuncSetAttribute(made_kernel,
                       cudaFuncAttributeMaxDynamicSharedMemorySize, smemA);

  // zero the log-det accumulator region (graph-capturable async memset)
  cudaMemsetAsync(out + (size_t)B*64, 0, (size_t)B * sizeof(float));

  made_kernel<<<B/MR, MR, smemA>>>(x, W1, b1, W2, b2, B);
  spline_hi<<<dim3(B/128, 9), 256>>>(x, W3, b3, out, B);   // bigger kernel first
  spline_lo<<<dim3(B/128, 7), 256>>>(x, W3, b3, out, B);   // fills hi's tail
}